// round 12
// baseline (speedup 1.0000x reference)
#include <cuda_runtime.h>
#include <cuda_fp16.h>
#include <cstdint>
#include <math.h>

#define NN  64
#define SSS 5
#define AA  81
#define JP  264
#define NT  512          // threads per CTA

// smem byte offsets
#define SM_BH    0         // 256x512B  W_hh fp16 swizzled   (131072)
#define SM_AH    131072    // 128x512B  h fp16 swizzled      (65536)
#define SM_AX    196608    // 128x32B   x fp16               (4096)
#define SM_BX    200704    // 256x32B   W_ih fp16            (8192)
#define SM_BIAS  208896    // 256 f32                        (1024)
#define SM_STAGE 209920    // 128x128B  h staging            (16384)
#define SM_ORD   226304    // u8[32][64]                     (2048)
#define SM_MB    228352    // 10 mbarriers (80B)
#define SMEM_TOT 228480
// mbarrier slots (byte offsets from SM_MB)
#define MB_FULL(s)  (SM_MB + (s)*8)        // count 1  : slice s of A_h ready
#define MB_FULLX    (SM_MB + 32)           // count 4  : A_x ready
#define MB_DONE(s)  (SM_MB + 40 + (s)*8)   // count 64 : slice s consumed (at CTA s)
#define MB_DONEX    (SM_MB + 72)           // count 16 : A_x row-slice consumed (at owner)
// head overlays (post-loop)
#define SM_JOINT 0
#define SM_O2    36864
#define SM_O1    131072

// ---------------- helpers ----------------
__device__ __forceinline__ uint32_t smem_u32(const void* p){
  uint32_t a; asm("{ .reg .u64 t; cvta.to.shared.u64 t, %1; cvt.u32.u64 %0, t; }" : "=r"(a) : "l"(p)); return a;
}
__device__ __forceinline__ uint32_t ctarank(){
  uint32_t r; asm("mov.u32 %0, %%cluster_ctarank;" : "=r"(r)); return r;
}
__device__ __forceinline__ uint32_t mapa_u32(uint32_t a, uint32_t rank){
  uint32_t r; asm("mapa.shared::cluster.u32 %0, %1, %2;" : "=r"(r) : "r"(a), "r"(rank)); return r;
}
__device__ __forceinline__ void st_cluster_v4(uint32_t a, uint4 v){
  asm volatile("st.shared::cluster.v4.b32 [%0], {%1,%2,%3,%4};"
               :: "r"(a), "r"(v.x), "r"(v.y), "r"(v.z), "r"(v.w) : "memory");
}
#define CLUSTER_SYNC() do { asm volatile("barrier.cluster.arrive.aligned;" ::: "memory"); \
                            asm volatile("barrier.cluster.wait.aligned;" ::: "memory"); } while(0)
#define MBAR_INIT(mb,c) asm volatile("mbarrier.init.shared.b64 [%0], %1;" :: "r"(mb), "r"((uint32_t)(c)) : "memory")
__device__ __forceinline__ void mbar_arrive_remote(uint32_t local_mb, uint32_t rank){
  uint32_t rem = mapa_u32(local_mb, rank);
  asm volatile("mbarrier.arrive.shared::cluster.b64 _, [%0];" :: "r"(rem) : "memory");
}
#define MBAR_WAIT(mb,par) do { uint32_t _m=(mb),_p=(par),_d; \
  asm volatile("{\n .reg .pred p;\n mbarrier.try_wait.parity.acquire.cta.shared::cta.b64 p, [%1], %2;\n selp.b32 %0,1,0,p;\n}" : "=r"(_d) : "r"(_m), "r"(_p) : "memory"); \
  if(!_d){ asm volatile("{\n .reg .pred P1;\nWL_%=:\n mbarrier.try_wait.parity.acquire.cta.shared::cta.b64 P1, [%0], %1, 0x989680;\n @P1 bra.uni WD_%=;\n bra.uni WL_%=;\nWD_%=:\n}" :: "r"(_m), "r"(_p) : "memory"); } } while(0)

__device__ __forceinline__ uint32_t elect1(){
  uint32_t p; asm volatile("{\n .reg .pred p;\n elect.sync _|p, 0xFFFFFFFF;\n selp.b32 %0,1,0,p;\n}" : "=r"(p)); return p;
}
__device__ __forceinline__ void ldm4(uint32_t* r, uint32_t addr){
  asm volatile("ldmatrix.sync.aligned.m8n8.x4.shared.b16 {%0,%1,%2,%3}, [%4];"
    : "=r"(r[0]), "=r"(r[1]), "=r"(r[2]), "=r"(r[3]) : "r"(addr));
}
__device__ __forceinline__ void mma16816(float* d, const uint32_t* a, uint32_t b0, uint32_t b1){
  asm volatile("mma.sync.aligned.m16n8k16.row.col.f32.f16.f16.f32 "
    "{%0,%1,%2,%3}, {%4,%5,%6,%7}, {%8,%9}, {%0,%1,%2,%3};"
    : "+f"(d[0]), "+f"(d[1]), "+f"(d[2]), "+f"(d[3])
    : "r"(a[0]), "r"(a[1]), "r"(a[2]), "r"(a[3]), "r"(b0), "r"(b1));
}
__device__ __forceinline__ float tanha(float x){
  float r; asm("tanh.approx.f32 %0, %1;" : "=f"(r) : "f"(x)); return r;
}
__device__ __forceinline__ float siga(float x){ return fmaf(tanha(x*0.5f), 0.5f, 0.5f); }

__device__ __forceinline__ unsigned long long packf2(float lo, float hi){
  unsigned long long r; asm("mov.b64 %0, {%1, %2};" : "=l"(r) : "f"(lo), "f"(hi)); return r;
}
__device__ __forceinline__ void unpackf2(unsigned long long v, float& lo, float& hi){
  asm("mov.b64 {%0, %1}, %2;" : "=f"(lo), "=f"(hi) : "l"(v));
}
__device__ __forceinline__ unsigned long long fma2(unsigned long long a, unsigned long long b, unsigned long long c){
  unsigned long long d; asm("fma.rn.f32x2 %0, %1, %2, %3;" : "=l"(d) : "l"(a), "l"(b), "l"(c)); return d;
}

// ---- single fused kernel: sort + convert + clustered mma LSTM + head ----
__global__ void __launch_bounds__(NT,1) __cluster_dims__(4,1,1)
lstm_cluster(const float* __restrict__ state,
             const float* __restrict__ Wih, const float* __restrict__ Whh,
             const float* __restrict__ bih, const float* __restrict__ bhh,
             const float* __restrict__ W1, const float* __restrict__ b1,
             const float* __restrict__ W2, const float* __restrict__ b2,
             const float* __restrict__ Wv, const float* __restrict__ bv,
             float* __restrict__ out){
  extern __shared__ __align__(128) char smem[];
  uint32_t sb = smem_u32(smem);
  int tid = threadIdx.x, w = tid>>5, lane = tid&31;
  uint32_t p = ctarank();
  int tile = blockIdx.x >> 2;
  unsigned char* ord = (unsigned char*)(smem + SM_ORD);

  // ---- prologue: sort own 32 rows (ds temp in STAGE) ----
  {
    float* ds = (float*)(smem + SM_STAGE);
    for (int i = tid; i < 2048; i += NT){
      int r = i>>6, n = i&63;
      const float* row = state + ((size_t)(tile*128 + (int)p*32 + r)*64 + n)*12;
      float s5 = row[5], s6 = row[6];
      ds[i] = (s5 != 0.0f && s6 != 0.0f) ? sqrtf(s5*s5 + s6*s6) : __int_as_float(0x7f800000);
    }
    __syncthreads();
    for (int i = tid; i < 2048; i += NT){
      int r = i>>6, n = i&63;
      float d = ds[r*64 + n]; int rank = 0;
      #pragma unroll 8
      for (int j = 0; j < 64; j++){
        float dj = ds[r*64 + j];
        rank += (int)((dj > d) || (dj == d && j < n));
      }
      ord[r*64 + rank] = (unsigned char)n;
    }
    __syncthreads();
  }

  // ---- prologue: W_hh fp16 swizzled, bias, W_ih, zero A_h/A_x, mbarriers ----
  {
    uint4 z = make_uint4(0,0,0,0);
    for (int i = tid; i < (65536+4096)/16; i += NT) ((uint4*)(smem + SM_AH))[i] = z;
    for (int i = tid; i < 8192/16;        i += NT) ((uint4*)(smem + SM_BX))[i] = z;
    __syncthreads();
    for (int i = tid; i < 32768; i += NT){
      int n = i>>7, kw = i&127;
      int j = n>>2, g = n&3;
      float2 v = *(const float2*)(Whh + (size_t)(g*256 + (int)p*64 + j)*256 + kw*2);
      __half2 h2 = __floats2half2_rn(v.x, v.y);
      uint32_t off = (uint32_t)(n*512 + ((kw*4) ^ ((n&7)<<4)));
      *(uint32_t*)(smem + SM_BH + off) = *(uint32_t*)&h2;
    }
    for (int i = tid; i < 256; i += NT){
      int j = i>>2, g = i&3, gr = g*256 + (int)p*64 + j;
      ((float*)(smem + SM_BIAS))[i] = bih[gr] + bhh[gr];
    }
    for (int i = tid; i < 256*7; i += NT){
      int n = i/7, kx = i - n*7;
      int gr = (n&3)*256 + (int)p*64 + (n>>2);
      *(__half*)(smem + SM_BX + n*32 + kx*2) = __float2half_rn(Wih[gr*7 + kx]);
    }
    if (tid == 0){
      #pragma unroll
      for (int s = 0; s < 4; s++){
        MBAR_INIT(sb + MB_FULL(s), 1);
        MBAR_INIT(sb + MB_DONE(s), 64);
      }
      MBAR_INIT(sb + MB_FULLX, 4);
      MBAR_INIT(sb + MB_DONEX, 16);
    }
  }
  __syncthreads();

  uint32_t peerAH[4];
  #pragma unroll
  for (int q2 = 0; q2 < 4; q2++) peerAH[q2] = mapa_u32(sb + SM_AH, q2);

  // A_x for t=0: own 32 rows -> all peers
  if (tid < 32){
    int r = tid;
    const float* xp = state + ((size_t)(tile*128 + (int)p*32 + r)*64 + ord[r*64 + 0])*12 + SSS;
    __align__(16) __half hx[8];
    #pragma unroll
    for (int k = 0; k < 7; k++) hx[k] = __float2half_rn(xp[k]);
    hx[7] = __float2half_rn(0.0f);
    uint4 v = *(uint4*)hx;
    uint32_t off = (uint32_t)((SM_AX - SM_AH) + ((int)p*32 + r)*32);
    #pragma unroll
    for (int q2 = 0; q2 < 4; q2++) st_cluster_v4(peerAH[q2] + off, v);
  }
  __syncthreads();
  CLUSTER_SYNC();     // inits + t=0 data visible cluster-wide

  // prime full flags (phase 0)
  if (tid == 0){
    #pragma unroll
    for (int q2 = 0; q2 < 4; q2++){
      mbar_arrive_remote(sb + MB_FULL((int)p), (uint32_t)q2);
      mbar_arrive_remote(sb + MB_FULLX, (uint32_t)q2);
    }
  }

  // warp tiling: 4 (M) x 4 (N); warp tile M=32, N=64
  int m0 = (w>>2)*32;
  int nb = (w&3)*64;
  int q  = lane&3;
  int lr = lane>>2;
  float creg[16];
  #pragma unroll
  for (int i = 0; i < 16; i++) creg[i] = 0.0f;
  const float* bias = (const float*)(smem + SM_BIAS);

  for (int t = 0; t < NN; t++){
    int ph = t & 1;
    float acc[2][8][4];
    #pragma unroll
    for (int a = 0; a < 2; a++)
      #pragma unroll
      for (int b = 0; b < 8; b++){ acc[a][b][0]=0.f; acc[a][b][1]=0.f; acc[a][b][2]=0.f; acc[a][b][3]=0.f; }

    // ---- x chunk first (earliest-available data; frees DONEX early) ----
    MBAR_WAIT(sb + MB_FULLX, ph);
    {
      uint32_t axr[2][4], bxr[4][4];
      #pragma unroll
      for (int mt = 0; mt < 2; mt++){
        int row = m0 + mt*16 + (lane&15);
        ldm4(axr[mt], sb + SM_AX + row*32 + (lane>>4)*16);
      }
      #pragma unroll
      for (int bt = 0; bt < 4; bt++){
        int nr = nb + bt*16 + (lane&7) + ((lane>>4)<<3);
        ldm4(bxr[bt], sb + SM_BX + nr*32 + ((lane>>3)&1)*16);
      }
      #pragma unroll
      for (int mt = 0; mt < 2; mt++)
        #pragma unroll
        for (int bt = 0; bt < 4; bt++){
          mma16816(acc[mt][bt*2+0], axr[mt], bxr[bt][0], bxr[bt][1]);
          mma16816(acc[mt][bt*2+1], axr[mt], bxr[bt][2], bxr[bt][3]);
        }
      if (elect1()) mbar_arrive_remote(sb + MB_DONEX, (uint32_t)(w>>2));
    }

    // ---- 16 h chunks: A double-buffered, B loaded across waits (B is t-invariant) ----
    {
      uint32_t bfr[4][4];       // single B buffer (reloaded WAR after mma issue)
      uint32_t afr[2][2][4];    // A double buffer
      // preload B for group 0 chunk 0 (kb = p*128); safe before wait: W_hh static
      {
        int kb = (int)p * 128;
        #pragma unroll
        for (int bt = 0; bt < 4; bt++){
          int nr = nb + bt*16 + (lane&7) + ((lane>>4)<<3);
          ldm4(bfr[bt], sb + SM_BH + nr*512 + (((uint32_t)(kb + ((lane>>3)&1)*16)) ^ ((nr&7)<<4)));
        }
      }
      #pragma unroll
      for (int i = 0; i < 4; i++){
        int s = ((int)p + i) & 3;
        MBAR_WAIT(sb + MB_FULL(s), ph);
        // A chunk j=0 into buffer 0
        #pragma unroll
        for (int mt = 0; mt < 2; mt++){
          int row = m0 + mt*16 + (lane&15);
          ldm4(afr[0][mt], sb + SM_AH + row*512 + (((uint32_t)(s*128 + (lane>>4)*16)) ^ ((row&7)<<4)));
        }
        #pragma unroll
        for (int j = 0; j < 4; j++){
          // prefetch next A chunk (same slice) into alternate buffer
          if (j < 3){
            int kbn = (s*4 + j + 1)*32;
            #pragma unroll
            for (int mt = 0; mt < 2; mt++){
              int row = m0 + mt*16 + (lane&15);
              ldm4(afr[(j+1)&1][mt], sb + SM_AH + row*512 + (((uint32_t)(kbn + (lane>>4)*16)) ^ ((row&7)<<4)));
            }
          }
          // mma on current fragments
          #pragma unroll
          for (int mt = 0; mt < 2; mt++)
            #pragma unroll
            for (int bt = 0; bt < 4; bt++){
              mma16816(acc[mt][bt*2+0], afr[j&1][mt], bfr[bt][0], bfr[bt][1]);
              mma16816(acc[mt][bt*2+1], afr[j&1][mt], bfr[bt][2], bfr[bt][3]);
            }
          // reload B for next chunk (WAR over just-issued mma); crosses the next wait
          if (j < 3 || i < 3){
            int kbn2 = (j < 3) ? (s*4 + j + 1)*32 : ((((int)p + i + 1) & 3)*128);
            #pragma unroll
            for (int bt = 0; bt < 4; bt++){
              int nr = nb + bt*16 + (lane&7) + ((lane>>4)<<3);
              ldm4(bfr[bt], sb + SM_BH + nr*512 + (((uint32_t)(kbn2 + ((lane>>3)&1)*16)) ^ ((nr&7)<<4)));
            }
          }
        }
        if (elect1()) mbar_arrive_remote(sb + MB_DONE(s), (uint32_t)s);
      }
    }

    // prefetch next x (threads 0-31), overlapped with epilogue math
    float xf[7];
    bool have = (t < NN-1) && (tid < 32);
    if (have){
      const float* xp = state + ((size_t)(tile*128 + (int)p*32 + tid)*64 + ord[tid*64 + (t+1)])*12 + SSS;
      #pragma unroll
      for (int k = 0; k < 7; k++) xf[k] = xp[k];
    }

    // epilogue: gates -> cell update -> h staging
    #pragma unroll
    for (int mt = 0; mt < 2; mt++)
      #pragma unroll
      for (int nt = 0; nt < 8; nt++){
        float c0 = acc[mt][nt][0], c1 = acc[mt][nt][1], c2 = acc[mt][nt][2], c3 = acc[mt][nt][3];
        float sa = (q&1) ? c0 : c2;
        float sv = (q&1) ? c1 : c3;
        float ra = __shfl_xor_sync(0xFFFFFFFFu, sa, 1);
        float rb = __shfl_xor_sync(0xFFFFFFFFu, sv, 1);
        float gi, gf, gg, go;
        if (q&1){ gi = ra; gf = rb; gg = c2; go = c3; }
        else    { gi = c0; gf = c1; gg = ra; go = rb; }
        int jf = (nb>>2) + nt*2 + (q>>1);
        float4 bs = *(const float4*)(bias + jf*4);
        gi += bs.x; gf += bs.y; gg += bs.z; go += bs.w;
        int s = mt*8 + nt;
        float cn = siga(gf)*creg[s] + siga(gi)*tanha(gg);
        creg[s] = cn;
        float hv = siga(go)*tanha(cn);
        int rowf = m0 + mt*16 + lr + ((q&1)<<3);
        *(__half*)(smem + SM_STAGE + rowf*128 + jf*2) = __float2half_rn(hv);
      }
    __syncthreads();                 // stage complete (CTA-local)

    // overwrite guard: all 64 warp-reads of my h slice done
    MBAR_WAIT(sb + MB_DONE((int)p), ph);
    for (int cidx = tid; cidx < 1024; cidx += NT){
      int m = cidx>>3, jb = cidx&7;
      uint4 v = *(const uint4*)(smem + SM_STAGE + m*128 + jb*16);
      uint32_t off = (uint32_t)(m*512 + (((p<<7) + jb*16) ^ ((m&7)<<4)));
      #pragma unroll
      for (int q2 = 0; q2 < 4; q2++) st_cluster_v4(peerAH[q2] + off, v);
    }
    if (have){
      MBAR_WAIT(sb + MB_DONEX, ph);  // all readers of my x rows done
      __align__(16) __half hx[8];
      #pragma unroll
      for (int k = 0; k < 7; k++) hx[k] = __float2half_rn(xf[k]);
      hx[7] = __float2half_rn(0.0f);
      uint4 v = *(uint4*)hx;
      uint32_t off = (uint32_t)((SM_AX - SM_AH) + ((int)p*32 + tid)*32);
      #pragma unroll
      for (int q2 = 0; q2 < 4; q2++) st_cluster_v4(peerAH[q2] + off, v);
    }
    __syncthreads();                 // all my dist writes issued
    if (tid == 0 && t < NN-1){
      #pragma unroll
      for (int q2 = 0; q2 < 4; q2++){
        mbar_arrive_remote(sb + MB_FULL((int)p), (uint32_t)q2);
        mbar_arrive_remote(sb + MB_FULLX, (uint32_t)q2);
      }
    }
  }
  CLUSTER_SYNC();   // final h (t=63) visible everywhere before head reads A_h

  // ---------------- fused MLP head: 32 rows per CTA ----------------
  float* joint = (float*)(smem + SM_JOINT);
  float* o1    = (float*)(smem + SM_O1);
  float* o2    = (float*)(smem + SM_O2);
  for (int i = tid; i < 32*261; i += NT){
    int r = i/261, k = i - r*261;
    float v;
    if (k < SSS) v = state[(size_t)(tile*128 + (int)p*32 + r)*768 + k];
    else {
      int m = (int)p*32 + r, kk = k - SSS;
      uint32_t off = (uint32_t)(m*512 + (((uint32_t)(kk*2)) ^ ((m&7)<<4)));
      v = __half2float(*(const __half*)(smem + SM_AH + off));
    }
    joint[r*JP + k] = v;
  }
  __syncthreads();
  {
    int ct = tid & 127, rb = (tid>>7)*8;
    ulonglong2 bb = ((const ulonglong2*)b1)[ct];
    unsigned long long a1[8][2];
    #pragma unroll
    for (int r = 0; r < 8; r++){ a1[r][0] = bb.x; a1[r][1] = bb.y; }
    for (int k = 0; k < 261; k++){
      ulonglong2 wv = ((const ulonglong2*)W1)[k*128 + ct];
      #pragma unroll
      for (int r = 0; r < 8; r++){
        float av = joint[(rb + r)*JP + k];
        unsigned long long ap = packf2(av, av);
        a1[r][0] = fma2(wv.x, ap, a1[r][0]);
        a1[r][1] = fma2(wv.y, ap, a1[r][1]);
      }
    }
    __syncthreads();
    #pragma unroll
    for (int r = 0; r < 8; r++){
      float4 o; unpackf2(a1[r][0], o.x, o.y); unpackf2(a1[r][1], o.z, o.w);
      o.x = fmaxf(o.x,0.f); o.y = fmaxf(o.y,0.f); o.z = fmaxf(o.z,0.f); o.w = fmaxf(o.w,0.f);
      *(float4*)(o1 + (rb + r)*512 + ct*4) = o;
    }
  }
  __syncthreads();
  {
    int ct = tid & 127, rb = (tid>>7)*8;
    ulonglong2 bb = ((const ulonglong2*)b2)[ct];
    unsigned long long a1[8][2];
    #pragma unroll
    for (int r = 0; r < 8; r++){ a1[r][0] = bb.x; a1[r][1] = bb.y; }
    for (int k = 0; k < 512; k++){
      ulonglong2 wv = ((const ulonglong2*)W2)[k*128 + ct];
      #pragma unroll
      for (int r = 0; r < 8; r++){
        float av = o1[(rb + r)*512 + k];
        unsigned long long ap = packf2(av, av);
        a1[r][0] = fma2(wv.x, ap, a1[r][0]);
        a1[r][1] = fma2(wv.y, ap, a1[r][1]);
      }
    }
    __syncthreads();
    #pragma unroll
    for (int r = 0; r < 8; r++){
      float4 o; unpackf2(a1[r][0], o.x, o.y); unpackf2(a1[r][1], o.z, o.w);
      o.x = fmaxf(o.x,0.f); o.y = fmaxf(o.y,0.f); o.z = fmaxf(o.z,0.f); o.w = fmaxf(o.w,0.f);
      *(float4*)(o2 + (rb + r)*512 + ct*4) = o;
    }
  }
  __syncthreads();
  for (int i = tid; i < 32*AA; i += NT){
    int r = i/AA, col = i - r*AA;
    float acc = bv[col];
    const float* act = o2 + r*512;
    #pragma unroll 4
    for (int k = 0; k < 512; k++) acc = fmaf(act[k], Wv[k*AA + col], acc);
    out[(size_t)(tile*128 + (int)p*32 + r)*AA + col] = acc;
  }
}

extern "C" void kernel_launch(void* const* d_in, const int* in_sizes, int n_in,
                              void* d_out, int out_size){
  (void)in_sizes; (void)n_in; (void)out_size;
  const float* state = (const float*)d_in[0];
  const float* W_ih  = (const float*)d_in[1];
  const float* W_hh  = (const float*)d_in[2];
  const float* b_ih  = (const float*)d_in[3];
  const float* b_hh  = (const float*)d_in[4];
  const float* W1    = (const float*)d_in[5];
  const float* b1    = (const float*)d_in[6];
  const float* W2    = (const float*)d_in[7];
  const float* b2    = (const float*)d_in[8];
  const float* Wv    = (const float*)d_in[9];
  const float* bv    = (const float*)d_in[10];
  float* out = (float*)d_out;

  cudaFuncSetAttribute(lstm_cluster, cudaFuncAttributeMaxDynamicSharedMemorySize, SMEM_TOT);

  lstm_cluster<<<128, NT, SMEM_TOT>>>(state, W_ih, W_hh, b_ih, b_hh,
                                      W1, b1, W2, b2, Wv, bv, out);
}

// round 13
// speedup vs baseline: 1.0500x; 1.0500x over previous
#include <cuda_runtime.h>
#include <cuda_fp16.h>
#include <cstdint>
#include <math.h>

#define NN  64
#define SSS 5
#define AA  81
#define JP  264
#define NT  512          // threads per CTA

// smem byte offsets
#define SM_BH    0         // 256x512B  W_hh fp16 swizzled   (131072)
#define SM_AH    131072    // 128x512B  h fp16 swizzled      (65536)
#define SM_AX    196608    // 128x32B   x fp16               (4096)
#define SM_BX    200704    // 256x32B   W_ih fp16            (8192)
#define SM_BIAS  208896    // 256 f32                        (1024)
#define SM_STAGE 209920    // 128x128B  h staging            (16384)
#define SM_ORD   226304    // u8[32][64]                     (2048)
#define SM_MB    228352    // 24 mbarriers (192B)
#define SMEM_TOT 228544
// mbarrier slots: per-half h, slice s / per-owner pp
#define MB_FULL2(h,s) (SM_MB + ((h)*4+(s))*8)        // cnt 1 : A_h slice (h,s) ready
#define MB_DONE2(h,s) (SM_MB + 64 + ((h)*4+(s))*8)   // cnt 32: slice consumed (at CTA s)
#define MB_FX(pp)     (SM_MB + 128 + (pp)*8)         // cnt 1 : A_x rows of owner pp ready
#define MB_DX(pp)     (SM_MB + 160 + (pp)*8)         // cnt 16: x rows consumed (at owner)
// head overlays (post-loop)
#define SM_JOINT 0
#define SM_O2    36864
#define SM_O1    131072

// ---------------- helpers ----------------
__device__ __forceinline__ uint32_t smem_u32(const void* p){
  uint32_t a; asm("{ .reg .u64 t; cvta.to.shared.u64 t, %1; cvt.u32.u64 %0, t; }" : "=r"(a) : "l"(p)); return a;
}
__device__ __forceinline__ uint32_t ctarank(){
  uint32_t r; asm("mov.u32 %0, %%cluster_ctarank;" : "=r"(r)); return r;
}
__device__ __forceinline__ uint32_t mapa_u32(uint32_t a, uint32_t rank){
  uint32_t r; asm("mapa.shared::cluster.u32 %0, %1, %2;" : "=r"(r) : "r"(a), "r"(rank)); return r;
}
__device__ __forceinline__ void st_cluster_v4(uint32_t a, uint4 v){
  asm volatile("st.shared::cluster.v4.b32 [%0], {%1,%2,%3,%4};"
               :: "r"(a), "r"(v.x), "r"(v.y), "r"(v.z), "r"(v.w) : "memory");
}
#define CLUSTER_SYNC() do { asm volatile("barrier.cluster.arrive.aligned;" ::: "memory"); \
                            asm volatile("barrier.cluster.wait.aligned;" ::: "memory"); } while(0)
#define HALF_BAR(h) asm volatile("bar.sync %0, %1;" :: "r"(1+(h)), "r"(256) : "memory")
#define MBAR_INIT(mb,c) asm volatile("mbarrier.init.shared.b64 [%0], %1;" :: "r"(mb), "r"((uint32_t)(c)) : "memory")
__device__ __forceinline__ void mbar_arrive_remote(uint32_t local_mb, uint32_t rank){
  uint32_t rem = mapa_u32(local_mb, rank);
  asm volatile("mbarrier.arrive.shared::cluster.b64 _, [%0];" :: "r"(rem) : "memory");
}
#define MBAR_WAIT(mb,par) do { uint32_t _m=(mb),_p=(par),_d; \
  asm volatile("{\n .reg .pred p;\n mbarrier.try_wait.parity.acquire.cta.shared::cta.b64 p, [%1], %2;\n selp.b32 %0,1,0,p;\n}" : "=r"(_d) : "r"(_m), "r"(_p) : "memory"); \
  if(!_d){ asm volatile("{\n .reg .pred P1;\nWL_%=:\n mbarrier.try_wait.parity.acquire.cta.shared::cta.b64 P1, [%0], %1, 0x989680;\n @P1 bra.uni WD_%=;\n bra.uni WL_%=;\nWD_%=:\n}" :: "r"(_m), "r"(_p) : "memory"); } } while(0)

__device__ __forceinline__ uint32_t elect1(){
  uint32_t p; asm volatile("{\n .reg .pred p;\n elect.sync _|p, 0xFFFFFFFF;\n selp.b32 %0,1,0,p;\n}" : "=r"(p)); return p;
}
__device__ __forceinline__ void ldm4(uint32_t* r, uint32_t addr){
  asm volatile("ldmatrix.sync.aligned.m8n8.x4.shared.b16 {%0,%1,%2,%3}, [%4];"
    : "=r"(r[0]), "=r"(r[1]), "=r"(r[2]), "=r"(r[3]) : "r"(addr));
}
__device__ __forceinline__ void mma16816(float* d, const uint32_t* a, uint32_t b0, uint32_t b1){
  asm volatile("mma.sync.aligned.m16n8k16.row.col.f32.f16.f16.f32 "
    "{%0,%1,%2,%3}, {%4,%5,%6,%7}, {%8,%9}, {%0,%1,%2,%3};"
    : "+f"(d[0]), "+f"(d[1]), "+f"(d[2]), "+f"(d[3])
    : "r"(a[0]), "r"(a[1]), "r"(a[2]), "r"(a[3]), "r"(b0), "r"(b1));
}
__device__ __forceinline__ float tanha(float x){
  float r; asm("tanh.approx.f32 %0, %1;" : "=f"(r) : "f"(x)); return r;
}
__device__ __forceinline__ float siga(float x){ return fmaf(tanha(x*0.5f), 0.5f, 0.5f); }

__device__ __forceinline__ unsigned long long packf2(float lo, float hi){
  unsigned long long r; asm("mov.b64 %0, {%1, %2};" : "=l"(r) : "f"(lo), "f"(hi)); return r;
}
__device__ __forceinline__ void unpackf2(unsigned long long v, float& lo, float& hi){
  asm("mov.b64 {%0, %1}, %2;" : "=f"(lo), "=f"(hi) : "l"(v));
}
__device__ __forceinline__ unsigned long long fma2(unsigned long long a, unsigned long long b, unsigned long long c){
  unsigned long long d; asm("fma.rn.f32x2 %0, %1, %2, %3;" : "=l"(d) : "l"(a), "l"(b), "l"(c)); return d;
}

// ---- single fused kernel: sort + convert + two independent half-LSTMs + head ----
__global__ void __launch_bounds__(NT,1) __cluster_dims__(4,1,1)
lstm_cluster(const float* __restrict__ state,
             const float* __restrict__ Wih, const float* __restrict__ Whh,
             const float* __restrict__ bih, const float* __restrict__ bhh,
             const float* __restrict__ W1, const float* __restrict__ b1,
             const float* __restrict__ W2, const float* __restrict__ b2,
             const float* __restrict__ Wv, const float* __restrict__ bv,
             float* __restrict__ out){
  extern __shared__ __align__(128) char smem[];
  uint32_t sb = smem_u32(smem);
  int tid = threadIdx.x, w = tid>>5, lane = tid&31;
  uint32_t p = ctarank();
  int tile = blockIdx.x >> 2;
  unsigned char* ord = (unsigned char*)(smem + SM_ORD);
  int h = w>>3;                 // half id: warps 0-7 -> rows 0-63, warps 8-15 -> rows 64-127
  int grp = w>>2;               // m-group (x owner rank)

  // ---- prologue: sort own 32 rows (ds temp in STAGE) ----
  {
    float* ds = (float*)(smem + SM_STAGE);
    for (int i = tid; i < 2048; i += NT){
      int r = i>>6, n = i&63;
      const float* row = state + ((size_t)(tile*128 + (int)p*32 + r)*64 + n)*12;
      float s5 = row[5], s6 = row[6];
      ds[i] = (s5 != 0.0f && s6 != 0.0f) ? sqrtf(s5*s5 + s6*s6) : __int_as_float(0x7f800000);
    }
    __syncthreads();
    for (int i = tid; i < 2048; i += NT){
      int r = i>>6, n = i&63;
      float d = ds[r*64 + n]; int rank = 0;
      #pragma unroll 8
      for (int j = 0; j < 64; j++){
        float dj = ds[r*64 + j];
        rank += (int)((dj > d) || (dj == d && j < n));
      }
      ord[r*64 + rank] = (unsigned char)n;
    }
    __syncthreads();
  }

  // ---- prologue: W_hh fp16 swizzled, bias, W_ih, zero A_h/A_x, mbarriers ----
  {
    uint4 z = make_uint4(0,0,0,0);
    for (int i = tid; i < (65536+4096)/16; i += NT) ((uint4*)(smem + SM_AH))[i] = z;
    for (int i = tid; i < 8192/16;        i += NT) ((uint4*)(smem + SM_BX))[i] = z;
    __syncthreads();
    for (int i = tid; i < 32768; i += NT){
      int n = i>>7, kw = i&127;
      int j = n>>2, g = n&3;
      float2 v = *(const float2*)(Whh + (size_t)(g*256 + (int)p*64 + j)*256 + kw*2);
      __half2 h2 = __floats2half2_rn(v.x, v.y);
      uint32_t off = (uint32_t)(n*512 + ((kw*4) ^ ((n&7)<<4)));
      *(uint32_t*)(smem + SM_BH + off) = *(uint32_t*)&h2;
    }
    for (int i = tid; i < 256; i += NT){
      int j = i>>2, g = i&3, gr = g*256 + (int)p*64 + j;
      ((float*)(smem + SM_BIAS))[i] = bih[gr] + bhh[gr];
    }
    for (int i = tid; i < 256*7; i += NT){
      int n = i/7, kx = i - n*7;
      int gr = (n&3)*256 + (int)p*64 + (n>>2);
      *(__half*)(smem + SM_BX + n*32 + kx*2) = __float2half_rn(Wih[gr*7 + kx]);
    }
    if (tid == 0){
      #pragma unroll
      for (int hh = 0; hh < 2; hh++)
        #pragma unroll
        for (int s = 0; s < 4; s++){
          MBAR_INIT(sb + MB_FULL2(hh,s), 1);
          MBAR_INIT(sb + MB_DONE2(hh,s), 32);
        }
      #pragma unroll
      for (int s = 0; s < 4; s++){
        MBAR_INIT(sb + MB_FX(s), 1);
        MBAR_INIT(sb + MB_DX(s), 16);
      }
    }
  }
  __syncthreads();

  uint32_t peerAH[4];
  #pragma unroll
  for (int q2 = 0; q2 < 4; q2++) peerAH[q2] = mapa_u32(sb + SM_AH, q2);

  // A_x for t=0: own 32 rows -> all peers
  if (tid < 32){
    int r = tid;
    const float* xp = state + ((size_t)(tile*128 + (int)p*32 + r)*64 + ord[r*64 + 0])*12 + SSS;
    __align__(16) __half hx[8];
    #pragma unroll
    for (int k = 0; k < 7; k++) hx[k] = __float2half_rn(xp[k]);
    hx[7] = __float2half_rn(0.0f);
    uint4 v = *(uint4*)hx;
    uint32_t off = (uint32_t)((SM_AX - SM_AH) + ((int)p*32 + r)*32);
    #pragma unroll
    for (int q2 = 0; q2 < 4; q2++) st_cluster_v4(peerAH[q2] + off, v);
  }
  __syncthreads();
  CLUSTER_SYNC();     // inits + t=0 data visible cluster-wide

  // prime full flags (phase 0): zeroed A_h (both halves) + t=0 A_x ready
  if (tid == 0){
    #pragma unroll
    for (int q2 = 0; q2 < 4; q2++){
      mbar_arrive_remote(sb + MB_FULL2(0,(int)p), (uint32_t)q2);
      mbar_arrive_remote(sb + MB_FULL2(1,(int)p), (uint32_t)q2);
      mbar_arrive_remote(sb + MB_FX((int)p), (uint32_t)q2);
    }
  }

  // warp tiling: 4 (M) x 4 (N); warp tile M=32, N=64
  int m0 = grp*32;
  int nb = (w&3)*64;
  int q  = lane&3;
  int lr = lane>>2;
  bool is_xwarp = (w == ((int)p>>1)*8) && (((int)p>>1) == h);  // first warp of owning half
  float creg[16];
  #pragma unroll
  for (int i = 0; i < 16; i++) creg[i] = 0.0f;
  const float* bias = (const float*)(smem + SM_BIAS);

  for (int t = 0; t < NN; t++){
    int ph = t & 1;
    float acc[2][8][4];
    #pragma unroll
    for (int a = 0; a < 2; a++)
      #pragma unroll
      for (int b = 0; b < 8; b++){ acc[a][b][0]=0.f; acc[a][b][1]=0.f; acc[a][b][2]=0.f; acc[a][b][3]=0.f; }

    // 16 K-chunks over h (own half's flags), own slice first
    #pragma unroll
    for (int i = 0; i < 4; i++){
      int s = ((int)p + i) & 3;
      MBAR_WAIT(sb + MB_FULL2(h,s), ph);
      #pragma unroll
      for (int j = 0; j < 4; j++){
        int kb = (s*4 + j)*32;
        uint32_t afr[2][4], bfr[4][4];
        #pragma unroll
        for (int mt = 0; mt < 2; mt++){
          int row = m0 + mt*16 + (lane&15);
          ldm4(afr[mt], sb + SM_AH + row*512 + (((uint32_t)(kb + (lane>>4)*16)) ^ ((row&7)<<4)));
        }
        #pragma unroll
        for (int bt = 0; bt < 4; bt++){
          int nr = nb + bt*16 + (lane&7) + ((lane>>4)<<3);
          ldm4(bfr[bt], sb + SM_BH + nr*512 + (((uint32_t)(kb + ((lane>>3)&1)*16)) ^ ((nr&7)<<4)));
        }
        #pragma unroll
        for (int mt = 0; mt < 2; mt++)
          #pragma unroll
          for (int bt = 0; bt < 4; bt++){
            mma16816(acc[mt][bt*2+0], afr[mt], bfr[bt][0], bfr[bt][1]);
            mma16816(acc[mt][bt*2+1], afr[mt], bfr[bt][2], bfr[bt][3]);
          }
      }
      if (elect1()) mbar_arrive_remote(sb + MB_DONE2(h,s), (uint32_t)s);
    }
    // x chunk (own m-group's owner flag)
    {
      MBAR_WAIT(sb + MB_FX(grp), ph);
      uint32_t afr[2][4], bfr[4][4];
      #pragma unroll
      for (int mt = 0; mt < 2; mt++){
        int row = m0 + mt*16 + (lane&15);
        ldm4(afr[mt], sb + SM_AX + row*32 + (lane>>4)*16);
      }
      #pragma unroll
      for (int bt = 0; bt < 4; bt++){
        int nr = nb + bt*16 + (lane&7) + ((lane>>4)<<3);
        ldm4(bfr[bt], sb + SM_BX + nr*32 + ((lane>>3)&1)*16);
      }
      #pragma unroll
      for (int mt = 0; mt < 2; mt++)
        #pragma unroll
        for (int bt = 0; bt < 4; bt++){
          mma16816(acc[mt][bt*2+0], afr[mt], bfr[bt][0], bfr[bt][1]);
          mma16816(acc[mt][bt*2+1], afr[mt], bfr[bt][2], bfr[bt][3]);
        }
      if (elect1()) mbar_arrive_remote(sb + MB_DX(grp), (uint32_t)grp);
    }

    // prefetch next x (x-warp lanes), overlapped with epilogue math
    float xf[7];
    bool have = (t < NN-1) && is_xwarp;
    if (have){
      const float* xp = state + ((size_t)(tile*128 + (int)p*32 + lane)*64 + ord[lane*64 + (t+1)])*12 + SSS;
      #pragma unroll
      for (int k = 0; k < 7; k++) xf[k] = xp[k];
    }

    // epilogue: gates -> cell update -> h staging
    #pragma unroll
    for (int mt = 0; mt < 2; mt++)
      #pragma unroll
      for (int nt = 0; nt < 8; nt++){
        float c0 = acc[mt][nt][0], c1 = acc[mt][nt][1], c2 = acc[mt][nt][2], c3 = acc[mt][nt][3];
        float sa = (q&1) ? c0 : c2;
        float sv = (q&1) ? c1 : c3;
        float ra = __shfl_xor_sync(0xFFFFFFFFu, sa, 1);
        float rb = __shfl_xor_sync(0xFFFFFFFFu, sv, 1);
        float gi, gf, gg, go;
        if (q&1){ gi = ra; gf = rb; gg = c2; go = c3; }
        else    { gi = c0; gf = c1; gg = ra; go = rb; }
        int jf = (nb>>2) + nt*2 + (q>>1);
        float4 bs = *(const float4*)(bias + jf*4);
        gi += bs.x; gf += bs.y; gg += bs.z; go += bs.w;
        int s = mt*8 + nt;
        float cn = siga(gf)*creg[s] + siga(gi)*tanha(gg);
        creg[s] = cn;
        float hv = siga(go)*tanha(cn);
        int rowf = m0 + mt*16 + lr + ((q&1)<<3);
        *(__half*)(smem + SM_STAGE + rowf*128 + jf*2) = __float2half_rn(hv);
      }
    HALF_BAR(h);                       // my half's stage complete

    // overwrite guard: all 32 half-h warp-reads of my h slice done
    MBAR_WAIT(sb + MB_DONE2(h,(int)p), ph);
    for (int cidx = (tid & 255); cidx < 512; cidx += 256){
      int m = h*64 + (cidx>>3), jb = cidx&7;
      uint4 v = *(const uint4*)(smem + SM_STAGE + m*128 + jb*16);
      uint32_t off = (uint32_t)(m*512 + (((p<<7) + jb*16) ^ ((m&7)<<4)));
      #pragma unroll
      for (int q2 = 0; q2 < 4; q2++) st_cluster_v4(peerAH[q2] + off, v);
    }
    if (have){
      MBAR_WAIT(sb + MB_DX((int)p), ph);   // all readers of my x rows done
      __align__(16) __half hx[8];
      #pragma unroll
      for (int k = 0; k < 7; k++) hx[k] = __float2half_rn(xf[k]);
      hx[7] = __float2half_rn(0.0f);
      uint4 v = *(uint4*)hx;
      uint32_t off = (uint32_t)((SM_AX - SM_AH) + ((int)p*32 + lane)*32);
      #pragma unroll
      for (int q2 = 0; q2 < 4; q2++) st_cluster_v4(peerAH[q2] + off, v);
    }
    HALF_BAR(h);                       // my half's dist writes issued
    if ((tid & 255) == 0 && t < NN-1){
      #pragma unroll
      for (int q2 = 0; q2 < 4; q2++){
        mbar_arrive_remote(sb + MB_FULL2(h,(int)p), (uint32_t)q2);
        if (((int)p>>1) == h) mbar_arrive_remote(sb + MB_FX((int)p), (uint32_t)q2);
      }
    }
  }
  __syncthreads();    // join halves
  CLUSTER_SYNC();     // final h visible everywhere before head reads A_h

  // ---------------- fused MLP head: 32 rows per CTA ----------------
  float* joint = (float*)(smem + SM_JOINT);
  float* o1    = (float*)(smem + SM_O1);
  float* o2    = (float*)(smem + SM_O2);
  for (int i = tid; i < 32*261; i += NT){
    int r = i/261, k = i - r*261;
    float v;
    if (k < SSS) v = state[(size_t)(tile*128 + (int)p*32 + r)*768 + k];
    else {
      int m = (int)p*32 + r, kk = k - SSS;
      uint32_t off = (uint32_t)(m*512 + (((uint32_t)(kk*2)) ^ ((m&7)<<4)));
      v = __half2float(*(const __half*)(smem + SM_AH + off));
    }
    joint[r*JP + k] = v;
  }
  __syncthreads();
  {
    int ct = tid & 127, rb = (tid>>7)*8;
    ulonglong2 bb = ((const ulonglong2*)b1)[ct];
    unsigned long long a1[8][2];
    #pragma unroll
    for (int r = 0; r < 8; r++){ a1[r][0] = bb.x; a1[r][1] = bb.y; }
    for (int k = 0; k < 261; k++){
      ulonglong2 wv = ((const ulonglong2*)W1)[k*128 + ct];
      #pragma unroll
      for (int r = 0; r < 8; r++){
        float av = joint[(rb + r)*JP + k];
        unsigned long long ap = packf2(av, av);
        a1[r][0] = fma2(wv.x, ap, a1[r][0]);
        a1[r][1] = fma2(wv.y, ap, a1[r][1]);
      }
    }
    __syncthreads();
    #pragma unroll
    for (int r = 0; r < 8; r++){
      float4 o; unpackf2(a1[r][0], o.x, o.y); unpackf2(a1[r][1], o.z, o.w);
      o.x = fmaxf(o.x,0.f); o.y = fmaxf(o.y,0.f); o.z = fmaxf(o.z,0.f); o.w = fmaxf(o.w,0.f);
      *(float4*)(o1 + (rb + r)*512 + ct*4) = o;
    }
  }
  __syncthreads();
  {
    int ct = tid & 127, rb = (tid>>7)*8;
    ulonglong2 bb = ((const ulonglong2*)b2)[ct];
    unsigned long long a1[8][2];
    #pragma unroll
    for (int r = 0; r < 8; r++){ a1[r][0] = bb.x; a1[r][1] = bb.y; }
    for (int k = 0; k < 512; k++){
      ulonglong2 wv = ((const ulonglong2*)W2)[k*128 + ct];
      #pragma unroll
      for (int r = 0; r < 8; r++){
        float av = o1[(rb + r)*512 + k];
        unsigned long long ap = packf2(av, av);
        a1[r][0] = fma2(wv.x, ap, a1[r][0]);
        a1[r][1] = fma2(wv.y, ap, a1[r][1]);
      }
    }
    __syncthreads();
    #pragma unroll
    for (int r = 0; r < 8; r++){
      float4 o; unpackf2(a1[r][0], o.x, o.y); unpackf2(a1[r][1], o.z, o.w);
      o.x = fmaxf(o.x,0.f); o.y = fmaxf(o.y,0.f); o.z = fmaxf(o.z,0.f); o.w = fmaxf(o.w,0.f);
      *(float4*)(o2 + (rb + r)*512 + ct*4) = o;
    }
  }
  __syncthreads();
  for (int i = tid; i < 32*AA; i += NT){
    int r = i/AA, col = i - r*AA;
    float acc = bv[col];
    const float* act = o2 + r*512;
    #pragma unroll 4
    for (int k = 0; k < 512; k++) acc = fmaf(act[k], Wv[k*AA + col], acc);
    out[(size_t)(tile*128 + (int)p*32 + r)*AA + col] = acc;
  }
}

extern "C" void kernel_launch(void* const* d_in, const int* in_sizes, int n_in,
                              void* d_out, int out_size){
  (void)in_sizes; (void)n_in; (void)out_size;
  const float* state = (const float*)d_in[0];
  const float* W_ih  = (const float*)d_in[1];
  const float* W_hh  = (const float*)d_in[2];
  const float* b_ih  = (const float*)d_in[3];
  const float* b_hh  = (const float*)d_in[4];
  const float* W1    = (const float*)d_in[5];
  const float* b1    = (const float*)d_in[6];
  const float* W2    = (const float*)d_in[7];
  const float* b2    = (const float*)d_in[8];
  const float* Wv    = (const float*)d_in[9];
  const float* bv    = (const float*)d_in[10];
  float* out = (float*)d_out;

  cudaFuncSetAttribute(lstm_cluster, cudaFuncAttributeMaxDynamicSharedMemorySize, SMEM_TOT);

  lstm_cluster<<<128, NT, SMEM_TOT>>>(state, W_ih, W_hh, b_ih, b_hh,
                                      W1, b1, W2, b2, Wv, bv, out);
}